// round 12
// baseline (speedup 1.0000x reference)
#include <cuda_runtime.h>
#include <math.h>

// Problem constants
#define R_    2048
#define C_    1024
#define NCH   8

#define RPB   16                 // rows per block
#define NB    (R_ / RPB)         // 128 blocks
#define NREP  4                  // L replicas (atomic contention spreading)

// Scratch (no allocations allowed -> device globals; zero-initialized at load)
__device__ float g_L[NREP][NCH * C_];   // accumulated L (atomics), 4 x 32KB
__device__ float g_pA[64 * NB];         // [i][block] partial sum_r P*s
__device__ float g_pB[64 * NB];         // [i][block] partial sum_r P
__device__ float g_pSel[NB];            // per-block row-sel partials
__device__ unsigned int g_count;        // ticket (finalizer resets)

// ---------------------------------------------------------------------------
// Single kernel, 128 blocks x 256 threads (R4's proven kf_fused core).
//  Stage A: 8 warps x 2 rows -> softmax over 64, write P, stage P/lq/sel.
//  Stage B: stream the 16x1024 D tile once; 4 cols/thread (float4), 32 accs,
//           per-row sums.
//  Stage C: RED.ADD accumulators into g_L[b&3] (no partial buffer!);
//           pA/pB/sel partials to global.
//  Ticket:  last block reads g_L (4 x 32KB, coalesced), 1-exp, per-ch sums,
//           reduces pA/pB/sel, writes scalars, re-zeroes g_L + ticket.
// Output layout: P[131072] | tot[8] | max_nnz[8] | num_col[8] | num_row[8] |
//                nnz_ch_ba[64] | col_density[8] | num_row_sel[1]
// ---------------------------------------------------------------------------
__global__ __launch_bounds__(256) void k_all(const float* __restrict__ W,
                                             const float* __restrict__ D,
                                             const float* __restrict__ G,
                                             float* __restrict__ out)
{
    __shared__ float sP[RPB][64];
    __shared__ float slq[RPB][NCH];
    __shared__ float sds[RPB][8];
    __shared__ float sSel[RPB];
    __shared__ float sS[RPB];

    const int t    = threadIdx.x;
    const int wid  = t >> 5;
    const int lane = t & 31;
    const int b    = blockIdx.x;
    const int r0   = b * RPB;

    const float2* W2 = reinterpret_cast<const float2*>(W);
    const float2* G2 = reinterpret_cast<const float2*>(G);

    // ---- Stage A: softmax, 2 rows per warp ----
    #pragma unroll
    for (int rr = 0; rr < 2; rr++) {
        const int rl = wid * 2 + rr;
        const int r  = r0 + rl;

        float2 w  = W2[r * 32 + lane];
        float2 gv = G2[r * 32 + lane];
        float e0 = w.x + gv.x;
        float e1 = w.y + gv.y;

        float m = fmaxf(e0, e1);
        #pragma unroll
        for (int o = 16; o > 0; o >>= 1)
            m = fmaxf(m, __shfl_xor_sync(0xFFFFFFFFu, m, o));

        float x0 = expf(e0 - m);
        float x1 = expf(e1 - m);
        float s  = x0 + x1;
        #pragma unroll
        for (int o = 16; o > 0; o >>= 1)
            s += __shfl_xor_sync(0xFFFFFFFFu, s, o);

        const float inv = 1.0f / s;      // == max(P): exp(0)=1 at the argmax
        const float p0  = x0 * inv;
        const float p1  = x1 * inv;

        reinterpret_cast<float2*>(out)[r * 32 + lane] = make_float2(p0, p1);
        sP[rl][2 * lane]     = p0;
        sP[rl][2 * lane + 1] = p1;

        float lq = log1pf(-p0) + log1pf(-p1);
        lq += __shfl_xor_sync(0xFFFFFFFFu, lq, 1);
        lq += __shfl_xor_sync(0xFFFFFFFFu, lq, 2);
        if ((lane & 3) == 0) slq[rl][lane >> 2] = lq;
        if (lane == 0) sSel[rl] = (inv > 0.99f) ? 1.0f : 0.0f;
    }
    __syncthreads();

    // ---- Stage B: single pass over the D tile ----
    float acc0[NCH], acc1[NCH], acc2[NCH], acc3[NCH];
    #pragma unroll
    for (int ch = 0; ch < NCH; ch++) { acc0[ch]=0.f; acc1[ch]=0.f; acc2[ch]=0.f; acc3[ch]=0.f; }
    float dsv[RPB];

    const float4* D4 = reinterpret_cast<const float4*>(D);
    #pragma unroll
    for (int rl = 0; rl < RPB; rl++) {
        float4 d = D4[(size_t)(r0 + rl) * 256 + t];
        dsv[rl] = (d.x + d.y) + (d.z + d.w);
        #pragma unroll
        for (int ch = 0; ch < NCH; ch++) {
            float l = slq[rl][ch];
            acc0[ch] = fmaf(d.x, l, acc0[ch]);
            acc1[ch] = fmaf(d.y, l, acc1[ch]);
            acc2[ch] = fmaf(d.z, l, acc2[ch]);
            acc3[ch] = fmaf(d.w, l, acc3[ch]);
        }
    }

    // per-row sums (after the memory loop)
    #pragma unroll
    for (int rl = 0; rl < RPB; rl++) {
        float v = dsv[rl];
        #pragma unroll
        for (int o = 16; o > 0; o >>= 1)
            v += __shfl_xor_sync(0xFFFFFFFFu, v, o);
        if (lane == 0) sds[rl][wid] = v;
    }

    // ---- Stage C: atomically accumulate L; write pA/pB/sel partials ----
    {
        float* Lrep = g_L[b & (NREP - 1)];
        const int c0 = t * 4;
        #pragma unroll
        for (int ch = 0; ch < NCH; ch++) {
            atomicAdd(&Lrep[ch * C_ + c0 + 0], acc0[ch]);
            atomicAdd(&Lrep[ch * C_ + c0 + 1], acc1[ch]);
            atomicAdd(&Lrep[ch * C_ + c0 + 2], acc2[ch]);
            atomicAdd(&Lrep[ch * C_ + c0 + 3], acc3[ch]);
        }
    }
    __syncthreads();

    if (t < RPB) {
        float v = 0.f;
        #pragma unroll
        for (int w2 = 0; w2 < 8; w2++) v += sds[t][w2];
        sS[t] = v;
    }
    __syncthreads();

    if (t < 64) {
        float a = 0.f, bb = 0.f;
        #pragma unroll
        for (int rl = 0; rl < RPB; rl++) {
            float p = sP[rl][t];
            bb += p;
            a   = fmaf(p, sS[rl], a);
        }
        g_pA[t * NB + b] = a;
        g_pB[t * NB + b] = bb;
    }
    if (t == 0) {
        float v = 0.f;
        #pragma unroll
        for (int rl = 0; rl < RPB; rl++) v += sSel[rl];
        g_pSel[b] = v;
    }

    // ---- completion ticket ----
    __shared__ int isLast;
    __threadfence();
    if (t == 0) {
        unsigned int old = atomicAdd(&g_count, 1u);
        isLast = (old == NB - 1) ? 1 : 0;
        if (isLast) g_count = 0;             // reset for next graph replay
    }
    __syncthreads();
    if (!isLast) return;
    __threadfence();                          // acquire all blocks' writes

    // ================= Finalize (last block only) =================
    __shared__ float snn[64], sps[64], sncol[NCH];
    __shared__ float ssel;

    // per-channel colch sums: warp wid owns channel wid
    {
        float nc = 0.f;
        #pragma unroll
        for (int j = 0; j < 32; j++) {
            const int c = lane + 32 * j;
            float L = g_L[0][wid * C_ + c] + g_L[1][wid * C_ + c]
                    + g_L[2][wid * C_ + c] + g_L[3][wid * C_ + c];
            nc += 1.0f - expf(L);
        }
        #pragma unroll
        for (int o = 16; o > 0; o >>= 1)
            nc += __shfl_xor_sync(0xFFFFFFFFu, nc, o);
        if (lane == 0) sncol[wid] = nc;
    }

    // nnz / psum: warp wid reduces outputs i = wid*8 .. wid*8+7
    #pragma unroll
    for (int k = 0; k < 8; k++) {
        const int i = wid * 8 + k;
        float va = g_pA[i * NB + lane]      + g_pA[i * NB + lane + 32]
                 + g_pA[i * NB + lane + 64] + g_pA[i * NB + lane + 96];
        float vb = g_pB[i * NB + lane]      + g_pB[i * NB + lane + 32]
                 + g_pB[i * NB + lane + 64] + g_pB[i * NB + lane + 96];
        #pragma unroll
        for (int o = 16; o > 0; o >>= 1) {
            va += __shfl_xor_sync(0xFFFFFFFFu, va, o);
            vb += __shfl_xor_sync(0xFFFFFFFFu, vb, o);
        }
        if (lane == 0) { snn[i] = va; sps[i] = vb; }
    }
    if (wid == 0) {                            // sel over 128 partials
        float v = g_pSel[lane]      + g_pSel[lane + 32]
                + g_pSel[lane + 64] + g_pSel[lane + 96];
        #pragma unroll
        for (int o = 16; o > 0; o >>= 1)
            v += __shfl_xor_sync(0xFFFFFFFFu, v, o);
        if (lane == 0) ssel = v;
    }
    __syncthreads();

    // re-zero g_L for the next graph replay (after all reads)
    {
        float4* Z = reinterpret_cast<float4*>(&g_L[0][0]);
        #pragma unroll
        for (int j = 0; j < (NREP * NCH * C_ / 4) / 256; j++)
            Z[t + 256 * j] = make_float4(0.f, 0.f, 0.f, 0.f);
    }

    if (t < 64) out[131104 + t] = snn[t];      // nnz_ch_ba

    if (t < NCH) {
        float m = -1e30f, ns = 0.f, rs = 0.f;
        #pragma unroll
        for (int ba = 0; ba < 8; ba++) {
            float nv = snn[t * 8 + ba];
            m  = fmaxf(m, nv);
            ns += nv;
            rs += sps[t * 8 + ba];
        }
        float ncl = sncol[t];
        out[131072 + t] = m + ncl + rs;        // tot_ch
        out[131080 + t] = m;                   // max_nnz_ch
        out[131088 + t] = ncl;                 // num_col_ch
        out[131096 + t] = rs;                  // num_row_ch
        out[131168 + t] = ns / rs / ncl;       // col_density_ch
    }
    if (t == 64) out[131176] = ssel;           // num_row_sel
}

// ---------------------------------------------------------------------------
extern "C" void kernel_launch(void* const* d_in, const int* in_sizes, int n_in,
                              void* d_out, int out_size)
{
    const float* W = (const float*)d_in[0];   // [2048, 64]
    const float* D = (const float*)d_in[1];   // [2048, 1024]
    const float* G = (const float*)d_in[2];   // [2048, 64]
    // d_in[3] = i, unused by the math
    float* out = (float*)d_out;

    k_all<<<NB, 256>>>(W, D, G, out);
}

// round 13
// speedup vs baseline: 1.6375x; 1.6375x over previous
#include <cuda_runtime.h>
#include <math.h>

// Problem constants
#define R_    2048
#define C_    1024
#define NCH   8

#define RPB   16                 // rows per block (phase 1)
#define NB    (R_ / RPB)         // 128 blocks

// Scratch (no allocations allowed -> device globals)
__device__ float g_Lpart[NB * NCH * C_];   // per-block partial log-sums (4MB)
__device__ float g_pA[64 * NB];            // [i][blk] partial sum_r P*s
__device__ float g_pB[64 * NB];            // [i][blk] partial sum_r P
__device__ float g_pSel[NB];               // per-block row-sel partials
__device__ float g_nnz[64];                // reduced nnz_ch_ba
__device__ float g_psum[64];               // reduced sum_r P
__device__ float g_ncolPart[NB];           // per-block colch sums
__device__ float g_selv;                   // reduced row-sel count
__device__ unsigned int g_done;            // barrier arrivals (reset at end)
__device__ unsigned int g_count;           // finalize ticket (reset at end)

// ---------------------------------------------------------------------------
// Single kernel, 128 blocks x 256 threads.
// Phase 1 (== R4 kf_fused): softmax (2 rows/warp), stream D tile once
//   (float4/thread), write Lpart + pA/pB/sel partials.
// Barrier: one atomicAdd arrival per block; warp 0 polls a volatile load.
// Phase 2 (== R4 k3, vectorized): block b reduces 64 outputs over 128
//   partials with float4 loads; colch=1-exp; spare work reduces pA/pB/sel.
// Ticket: last block writes the 105 scalars, resets counters.
// Output layout: P[131072] | tot[8] | max_nnz[8] | num_col[8] | num_row[8] |
//                nnz_ch_ba[64] | col_density[8] | num_row_sel[1]
// ---------------------------------------------------------------------------
__global__ __launch_bounds__(256) void k_all(const float* __restrict__ W,
                                             const float* __restrict__ D,
                                             const float* __restrict__ G,
                                             float* __restrict__ out)
{
    __shared__ float sP[RPB][64];
    __shared__ float slq[RPB][NCH];
    __shared__ float sds[RPB][8];
    __shared__ float sSel[RPB];
    __shared__ float sS[RPB];

    const int t    = threadIdx.x;
    const int wid  = t >> 5;
    const int lane = t & 31;
    const int b    = blockIdx.x;
    const int r0   = b * RPB;

    const float2* W2 = reinterpret_cast<const float2*>(W);
    const float2* G2 = reinterpret_cast<const float2*>(G);

    // ================= Phase 1 (R4 kf_fused) =================
    #pragma unroll
    for (int rr = 0; rr < 2; rr++) {
        const int rl = wid * 2 + rr;
        const int r  = r0 + rl;

        float2 w  = W2[r * 32 + lane];
        float2 gv = G2[r * 32 + lane];
        float e0 = w.x + gv.x;
        float e1 = w.y + gv.y;

        float m = fmaxf(e0, e1);
        #pragma unroll
        for (int o = 16; o > 0; o >>= 1)
            m = fmaxf(m, __shfl_xor_sync(0xFFFFFFFFu, m, o));

        float x0 = expf(e0 - m);
        float x1 = expf(e1 - m);
        float s  = x0 + x1;
        #pragma unroll
        for (int o = 16; o > 0; o >>= 1)
            s += __shfl_xor_sync(0xFFFFFFFFu, s, o);

        const float inv = 1.0f / s;      // == max(P): exp(0)=1 at the argmax
        const float p0  = x0 * inv;
        const float p1  = x1 * inv;

        reinterpret_cast<float2*>(out)[r * 32 + lane] = make_float2(p0, p1);
        sP[rl][2 * lane]     = p0;
        sP[rl][2 * lane + 1] = p1;

        float lq = log1pf(-p0) + log1pf(-p1);
        lq += __shfl_xor_sync(0xFFFFFFFFu, lq, 1);
        lq += __shfl_xor_sync(0xFFFFFFFFu, lq, 2);
        if ((lane & 3) == 0) slq[rl][lane >> 2] = lq;
        if (lane == 0) sSel[rl] = (inv > 0.99f) ? 1.0f : 0.0f;
    }
    __syncthreads();

    {
        float acc0[NCH], acc1[NCH], acc2[NCH], acc3[NCH];
        #pragma unroll
        for (int ch = 0; ch < NCH; ch++) { acc0[ch]=0.f; acc1[ch]=0.f; acc2[ch]=0.f; acc3[ch]=0.f; }
        float dsv[RPB];

        const float4* D4 = reinterpret_cast<const float4*>(D);
        #pragma unroll
        for (int rl = 0; rl < RPB; rl++) {
            float4 d = D4[(size_t)(r0 + rl) * 256 + t];
            dsv[rl] = (d.x + d.y) + (d.z + d.w);
            #pragma unroll
            for (int ch = 0; ch < NCH; ch++) {
                float l = slq[rl][ch];
                acc0[ch] = fmaf(d.x, l, acc0[ch]);
                acc1[ch] = fmaf(d.y, l, acc1[ch]);
                acc2[ch] = fmaf(d.z, l, acc2[ch]);
                acc3[ch] = fmaf(d.w, l, acc3[ch]);
            }
        }
        #pragma unroll
        for (int rl = 0; rl < RPB; rl++) {
            float v = dsv[rl];
            #pragma unroll
            for (int o = 16; o > 0; o >>= 1)
                v += __shfl_xor_sync(0xFFFFFFFFu, v, o);
            if (lane == 0) sds[rl][wid] = v;
        }

        const int c0 = t * 4;
        #pragma unroll
        for (int ch = 0; ch < NCH; ch++) {
            float4 v = make_float4(acc0[ch], acc1[ch], acc2[ch], acc3[ch]);
            *reinterpret_cast<float4*>(
                &g_Lpart[((size_t)b * NCH + ch) * C_ + c0]) = v;
        }
    }
    __syncthreads();

    if (t < RPB) {
        float v = 0.f;
        #pragma unroll
        for (int w2 = 0; w2 < 8; w2++) v += sds[t][w2];
        sS[t] = v;
    }
    __syncthreads();

    if (t < 64) {
        float a = 0.f, bb = 0.f;
        #pragma unroll
        for (int rl = 0; rl < RPB; rl++) {
            float p = sP[rl][t];
            bb += p;
            a   = fmaf(p, sS[rl], a);
        }
        g_pA[t * NB + b] = a;
        g_pB[t * NB + b] = bb;
    }
    if (t == 0) {
        float v = 0.f;
        #pragma unroll
        for (int rl = 0; rl < RPB; rl++) v += sSel[rl];
        g_pSel[b] = v;
    }

    // ================= Barrier (no RMW polling) =================
    __syncthreads();
    if (t == 0) { __threadfence(); atomicAdd(&g_done, 1u); }
    if (t < 32) {
        while (*(volatile unsigned int*)&g_done < NB) { }
    }
    __syncthreads();
    __threadfence();   // acquire all blocks' Lpart/pA/pB/sel writes

    // ================= Phase 2 (vectorized R4 k3) =================
    {
        // block b owns outputs o4 in [b*16, b*16+16) (float4 quads, one ch).
        // thread (q = t&15, pg = t>>4): sums 8 of 128 partials as float4.
        const int q  = t & 15;
        const int pg = t >> 4;            // 0..15
        const float4* Lp4 = reinterpret_cast<const float4*>(g_Lpart);
        const int o4 = b * 16 + q;
        float4 s = make_float4(0.f, 0.f, 0.f, 0.f);
        #pragma unroll
        for (int j = 0; j < 8; j++) {
            float4 v = Lp4[(size_t)(pg * 8 + j) * 2048 + o4];
            s.x += v.x; s.y += v.y; s.z += v.z; s.w += v.w;
        }
        __shared__ float4 s4[16][16];
        s4[pg][q] = s;
        __syncthreads();

        __shared__ float cs[2];
        if (t < 64) {
            const int ql = t >> 2, comp = t & 3;
            float L = 0.f;
            #pragma unroll
            for (int k = 0; k < 16; k++)
                L += reinterpret_cast<const float*>(&s4[k][ql])[comp];
            float colch = 1.0f - expf(L);
            #pragma unroll
            for (int o = 16; o > 0; o >>= 1)
                colch += __shfl_xor_sync(0xFFFFFFFFu, colch, o);
            if (lane == 0) cs[t >> 5] = colch;
        }

        // spare warps: reduce pA / pB / sel (coalesced rows of 128)
        if (wid == 4 && b < 64) {
            float a = g_pA[b * NB + lane]      + g_pA[b * NB + lane + 32]
                    + g_pA[b * NB + lane + 64] + g_pA[b * NB + lane + 96];
            #pragma unroll
            for (int o = 16; o > 0; o >>= 1)
                a += __shfl_xor_sync(0xFFFFFFFFu, a, o);
            if (lane == 0) g_nnz[b] = a;
        } else if (wid == 5 && b < 64) {
            float a = g_pB[b * NB + lane]      + g_pB[b * NB + lane + 32]
                    + g_pB[b * NB + lane + 64] + g_pB[b * NB + lane + 96];
            #pragma unroll
            for (int o = 16; o > 0; o >>= 1)
                a += __shfl_xor_sync(0xFFFFFFFFu, a, o);
            if (lane == 0) g_psum[b] = a;
        } else if (wid == 6 && b == 64) {
            float a = g_pSel[lane]      + g_pSel[lane + 32]
                    + g_pSel[lane + 64] + g_pSel[lane + 96];
            #pragma unroll
            for (int o = 16; o > 0; o >>= 1)
                a += __shfl_xor_sync(0xFFFFFFFFu, a, o);
            if (lane == 0) g_selv = a;
        }
        __syncthreads();
        if (t == 0) g_ncolPart[b] = cs[0] + cs[1];
    }

    // ================= Ticket finalize =================
    __shared__ int isLast;
    __threadfence();
    if (t == 0) {
        unsigned int old = atomicAdd(&g_count, 1u);
        isLast = (old == NB - 1) ? 1 : 0;
        if (isLast) { g_count = 0; g_done = 0; }   // reset for next replay
    }
    __syncthreads();
    if (!isLast) return;
    __threadfence();                                // acquire phase-2 writes

    if (t < 64) out[131104 + t] = g_nnz[t];         // nnz_ch_ba

    if (t < NCH) {
        float m = -1e30f, ns = 0.f, rs = 0.f;
        #pragma unroll
        for (int ba = 0; ba < 8; ba++) {
            float nv = g_nnz[t * 8 + ba];
            m  = fmaxf(m, nv);
            ns += nv;
            rs += g_psum[t * 8 + ba];
        }
        float ncl = 0.f;
        #pragma unroll
        for (int k = 0; k < 16; k++) ncl += g_ncolPart[t * 16 + k];
        out[131072 + t] = m + ncl + rs;             // tot_ch
        out[131080 + t] = m;                        // max_nnz_ch
        out[131088 + t] = ncl;                      // num_col_ch
        out[131096 + t] = rs;                       // num_row_ch
        out[131168 + t] = ns / rs / ncl;            // col_density_ch
    }
    if (t == 64) out[131176] = g_selv;              // num_row_sel
}

// ---------------------------------------------------------------------------
extern "C" void kernel_launch(void* const* d_in, const int* in_sizes, int n_in,
                              void* d_out, int out_size)
{
    const float* W = (const float*)d_in[0];   // [2048, 64]
    const float* D = (const float*)d_in[1];   // [2048, 1024]
    const float* G = (const float*)d_in[2];   // [2048, 64]
    // d_in[3] = i, unused by the math
    float* out = (float*)d_out;

    k_all<<<NB, 256>>>(W, D, G, out);
}